// round 10
// baseline (speedup 1.0000x reference)
#include <cuda_runtime.h>
#include <math.h>
#include <stdint.h>

#define EMBED 384
#define NHEADS 6
#define HS 64
#define BATCH 4
#define TT 2048
#define MTOK (BATCH * TT)   // 8192
#define ATTN_SCALE 0.125f   // 64^-0.5

// ---- scratch (no cudaMalloc allowed) ----
__device__ float g_Q[(size_t)BATCH * NHEADS * TT * HS];   // [B,H,T,64]
__device__ float g_cat[(size_t)MTOK * EMBED];
__device__ float g_t1[(size_t)MTOK * EMBED];
__device__ float g_x1[(size_t)MTOK * EMBED];
__device__ float g_t2[(size_t)MTOK * EMBED];

// ============================================================
// Tiled SGEMM: C[M,384] = A[M,384] @ W[384,384]^T (+bias)
// 128x64 CTA tile, 256 threads, 8x4 per-thread micro-tile.
// MODE 0: C = acc + bias
// MODE 1: C = relu(acc + bias)
// MODE 2: scatter acc into g_Q layout [B,H,T,64] (no bias)
// ============================================================
template <int MODE>
__global__ __launch_bounds__(256) void gemm384_kernel(
    const float* __restrict__ A, const float* __restrict__ W,
    const float* __restrict__ bias, float* __restrict__ C) {
  __shared__ float As[128][36];
  __shared__ float Bs[64][36];

  const int m0 = blockIdx.x * 128;
  const int n0 = blockIdx.y * 64;
  const int tid = threadIdx.x;
  const int tx = tid & 15;      // 16 -> N via tx + 16*j (j<4)
  const int ty = tid >> 4;      // 16 -> M via ty*8 + i (i<8)

  float acc[8][4];
#pragma unroll
  for (int i = 0; i < 8; i++)
#pragma unroll
    for (int j = 0; j < 4; j++) acc[i][j] = 0.0f;

  for (int k0 = 0; k0 < EMBED; k0 += 32) {
    // A tile: 128x32 = 1024 float4, 4/thread
#pragma unroll
    for (int q = 0; q < 4; q++) {
      int idx = tid + q * 256;
      int r = idx >> 3;                 // 0..127
      int c4 = (idx & 7) << 2;          // 0..28
      *(float4*)&As[r][c4] =
          *(const float4*)&A[(size_t)(m0 + r) * EMBED + k0 + c4];
    }
    // B tile: 64x32 = 512 float4, 2/thread
#pragma unroll
    for (int q = 0; q < 2; q++) {
      int idx = tid + q * 256;
      int r = idx >> 3;                 // 0..63
      int c4 = (idx & 7) << 2;
      *(float4*)&Bs[r][c4] =
          *(const float4*)&W[(size_t)(n0 + r) * EMBED + k0 + c4];
    }
    __syncthreads();

#pragma unroll
    for (int k4 = 0; k4 < 8; k4++) {
      float4 bv[4];
#pragma unroll
      for (int j = 0; j < 4; j++)
        bv[j] = *(float4*)&Bs[tx + 16 * j][k4 * 4];
#pragma unroll
      for (int i = 0; i < 8; i++) {
        float4 av = *(float4*)&As[ty * 8 + i][k4 * 4];
#pragma unroll
        for (int j = 0; j < 4; j++) {
          acc[i][j] += av.x * bv[j].x;
          acc[i][j] += av.y * bv[j].y;
          acc[i][j] += av.z * bv[j].z;
          acc[i][j] += av.w * bv[j].w;
        }
      }
    }
    __syncthreads();
  }

#pragma unroll
  for (int i = 0; i < 8; i++) {
    int m = m0 + ty * 8 + i;
#pragma unroll
    for (int j = 0; j < 4; j++) {
      int n = n0 + tx + 16 * j;
      float v = acc[i][j];
      if (MODE == 0) {
        C[(size_t)m * EMBED + n] = v + bias[n];
      } else if (MODE == 1) {
        C[(size_t)m * EMBED + n] = fmaxf(v + bias[n], 0.0f);
      } else {
        int b = m >> 11;            // /2048
        int t = m & 2047;
        int h = n >> 6;             // /64
        int d = n & 63;
        C[((size_t)(b * NHEADS + h) * TT + t) * HS + d] = v;
      }
    }
  }
}

// ============================================================
// Flash attention (fp32 SIMT), q = k = v (shared tensor).
// 128 query rows x 128 keys per tile iteration, 256 threads.
// S phase: 8x8 micro-tile; PV phase: 8x4 micro-tile.
// One shared K tile serves both S=Q*K^T and O+=P*K.
// Masking matches reference exactly: s = dot*scale; upper-tri -> -inf;
// any remaining s == 0.0f -> -inf.
// ============================================================
#define QROWS 128
#define ATTN_SMEM_FLOATS (QROWS * 64 + QROWS * 68 + QROWS * 128)
#define ATTN_SMEM_BYTES (ATTN_SMEM_FLOATS * 4)

__global__ __launch_bounds__(256) void attn_kernel(
    const float* __restrict__ Q, float* __restrict__ cat) {
  extern __shared__ float sm[];
  float* Qs = sm;                           // [128][64]
  float* Ks = sm + QROWS * 64;              // [128][68] padded
  float* Ps = sm + QROWS * 64 + QROWS * 68; // [128][128]

  const int bh = blockIdx.y;
  // big (high-qi) blocks first for wave balance
  const int qi = gridDim.x - 1 - blockIdx.x;
  const float* Qb = Q + (size_t)bh * TT * HS;

  const int tid = threadIdx.x;
  const int tx = tid & 15;
  const int ty = tid >> 4;

  // load Q tile (128x64 floats = 2048 float4, 8/thread)
#pragma unroll
  for (int q = 0; q < 8; q++) {
    int idx = tid + q * 256;
    int r = idx >> 4;                 // 0..127
    int c4 = (idx & 15) << 2;         // 0..60
    *(float4*)&Qs[r * 64 + c4] =
        *(const float4*)&Qb[(size_t)(qi * QROWS + r) * HS + c4];
  }

  float o[8][4];
  float mi[8], li[8];
#pragma unroll
  for (int i = 0; i < 8; i++) {
    mi[i] = -INFINITY;
    li[i] = 0.0f;
#pragma unroll
    for (int j = 0; j < 4; j++) o[i][j] = 0.0f;
  }

  for (int kt = 0; kt <= qi; kt++) {
    __syncthreads();  // protect Ks/Ps from previous iteration readers
#pragma unroll
    for (int q = 0; q < 8; q++) {
      int idx = tid + q * 256;
      int r = idx >> 4;
      int c4 = (idx & 15) << 2;
      *(float4*)&Ks[r * 68 + c4] =
          *(const float4*)&Qb[(size_t)(kt * QROWS + r) * HS + c4];
    }
    __syncthreads();

    // ---- S = Q * K^T  (128x128, 8 rows x 8 cols per thread) ----
    float s[8][8];
#pragma unroll
    for (int i = 0; i < 8; i++)
#pragma unroll
      for (int j = 0; j < 8; j++) s[i][j] = 0.0f;

#pragma unroll
    for (int d4 = 0; d4 < 16; d4++) {
      float4 bv[8];
#pragma unroll
      for (int j = 0; j < 8; j++)
        bv[j] = *(float4*)&Ks[(tx + 16 * j) * 68 + d4 * 4];
#pragma unroll
      for (int i = 0; i < 8; i++) {
        float4 av = *(float4*)&Qs[(ty * 8 + i) * 64 + d4 * 4];
#pragma unroll
        for (int j = 0; j < 8; j++) {
          s[i][j] += av.x * bv[j].x;
          s[i][j] += av.y * bv[j].y;
          s[i][j] += av.z * bv[j].z;
          s[i][j] += av.w * bv[j].w;
        }
      }
    }

    // ---- scale + mask (exact reference quirk) ----
#pragma unroll
    for (int i = 0; i < 8; i++) {
      int r = qi * QROWS + ty * 8 + i;
#pragma unroll
      for (int j = 0; j < 8; j++) {
        int c = kt * QROWS + tx + 16 * j;
        float v = s[i][j] * ATTN_SCALE;
        if (c > r || v == 0.0f) v = -INFINITY;
        s[i][j] = v;
      }
    }

    // ---- online softmax update ----
#pragma unroll
    for (int i = 0; i < 8; i++) {
      float rm = s[i][0];
#pragma unroll
      for (int j = 1; j < 8; j++) rm = fmaxf(rm, s[i][j]);
#pragma unroll
      for (int off = 8; off > 0; off >>= 1)
        rm = fmaxf(rm, __shfl_xor_sync(0xffffffffu, rm, off));
      float nm = fmaxf(mi[i], rm);
      float alpha = (mi[i] == -INFINITY) ? 0.0f : __expf(mi[i] - nm);
      float psum = 0.0f;
#pragma unroll
      for (int j = 0; j < 8; j++) {
        float p = __expf(s[i][j] - nm);
        s[i][j] = p;
        psum += p;
      }
#pragma unroll
      for (int off = 8; off > 0; off >>= 1)
        psum += __shfl_xor_sync(0xffffffffu, psum, off);
      li[i] = li[i] * alpha + psum;
      mi[i] = nm;
#pragma unroll
      for (int j = 0; j < 4; j++) o[i][j] *= alpha;
    }

    // ---- stage P, then O += P * V (V == K tile) ----
#pragma unroll
    for (int i = 0; i < 8; i++)
#pragma unroll
      for (int j = 0; j < 8; j++)
        Ps[(ty * 8 + i) * 128 + tx + 16 * j] = s[i][j];
    __syncthreads();

#pragma unroll
    for (int k4 = 0; k4 < 32; k4++) {
      float4 p4[8];
#pragma unroll
      for (int i = 0; i < 8; i++)
        p4[i] = *(float4*)&Ps[(ty * 8 + i) * 128 + k4 * 4];
#pragma unroll
      for (int kk = 0; kk < 4; kk++) {
        int k = k4 * 4 + kk;
        float v0 = Ks[k * 68 + tx];
        float v1 = Ks[k * 68 + tx + 16];
        float v2 = Ks[k * 68 + tx + 32];
        float v3 = Ks[k * 68 + tx + 48];
#pragma unroll
        for (int i = 0; i < 8; i++) {
          float pv = ((const float*)&p4[i])[kk];
          o[i][0] += pv * v0;
          o[i][1] += pv * v1;
          o[i][2] += pv * v2;
          o[i][3] += pv * v3;
        }
      }
    }
  }

  // ---- epilogue: normalize and write into concat layout [B,T,384] ----
  const int b = bh / NHEADS;
  const int h = bh % NHEADS;
#pragma unroll
  for (int i = 0; i < 8; i++) {
    float inv = 1.0f / li[i];
    int t = qi * QROWS + ty * 8 + i;
    size_t base = ((size_t)(b * TT + t)) * EMBED + h * HS;
#pragma unroll
    for (int j = 0; j < 4; j++)
      cat[base + tx + 16 * j] = o[i][j] * inv;
  }
}

// ============================================================
// out = LayerNorm(a + res) * g + be   (one block per token row)
// ============================================================
__global__ __launch_bounds__(128) void add_ln_kernel(
    const float* __restrict__ a, const float* __restrict__ res,
    const float* __restrict__ g, const float* __restrict__ be,
    float* __restrict__ out) {
  __shared__ float red[8];
  const int row = blockIdx.x;
  const int tid = threadIdx.x;
  const size_t base = (size_t)row * EMBED;

  float v[3];
#pragma unroll
  for (int q = 0; q < 3; q++) {
    int c = tid + q * 128;
    v[q] = a[base + c] + res[base + c];
  }

  float s = v[0] + v[1] + v[2];
#pragma unroll
  for (int off = 16; off > 0; off >>= 1)
    s += __shfl_xor_sync(0xffffffffu, s, off);
  if ((tid & 31) == 0) red[tid >> 5] = s;
  __syncthreads();
  float mu = (red[0] + red[1] + red[2] + red[3]) * (1.0f / EMBED);

  float d0 = v[0] - mu, d1 = v[1] - mu, d2 = v[2] - mu;
  float sq = d0 * d0 + d1 * d1 + d2 * d2;
#pragma unroll
  for (int off = 16; off > 0; off >>= 1)
    sq += __shfl_xor_sync(0xffffffffu, sq, off);
  if ((tid & 31) == 0) red[4 + (tid >> 5)] = sq;
  __syncthreads();
  float var = (red[4] + red[5] + red[6] + red[7]) * (1.0f / EMBED);
  float inv = rsqrtf(var + 1e-5f);

  out[base + tid]       = d0 * inv * g[tid]       + be[tid];
  out[base + tid + 128] = d1 * inv * g[tid + 128] + be[tid + 128];
  out[base + tid + 256] = d2 * inv * g[tid + 256] + be[tid + 256];
}

// ============================================================
// launch
// ============================================================
extern "C" void kernel_launch(void* const* d_in, const int* in_sizes, int n_in,
                              void* d_out, int out_size) {
  const float* x   = (const float*)d_in[0];
  const float* Wq  = (const float*)d_in[1];
  const float* Wo  = (const float*)d_in[2];
  const float* bo  = (const float*)d_in[3];
  const float* W1  = (const float*)d_in[4];
  const float* b1  = (const float*)d_in[5];
  const float* W2  = (const float*)d_in[6];
  const float* b2  = (const float*)d_in[7];
  const float* g1  = (const float*)d_in[8];
  const float* be1 = (const float*)d_in[9];
  const float* g2  = (const float*)d_in[10];
  const float* be2 = (const float*)d_in[11];
  float* out = (float*)d_out;

  float *pQ, *pcat, *pt1, *px1, *pt2;
  cudaGetSymbolAddress((void**)&pQ, g_Q);
  cudaGetSymbolAddress((void**)&pcat, g_cat);
  cudaGetSymbolAddress((void**)&pt1, g_t1);
  cudaGetSymbolAddress((void**)&px1, g_x1);
  cudaGetSymbolAddress((void**)&pt2, g_t2);

  cudaFuncSetAttribute(attn_kernel,
                       cudaFuncAttributeMaxDynamicSharedMemorySize,
                       ATTN_SMEM_BYTES);

  dim3 gemm_grid(MTOK / 128, EMBED / 64);

  // 1. q = x @ Wq^T, scattered to [B,H,T,64]
  gemm384_kernel<2><<<gemm_grid, 256>>>(x, Wq, nullptr, pQ);

  // 2. causal self-attention (q=k=v), output in concat layout
  attn_kernel<<<dim3(TT / QROWS, BATCH * NHEADS), 256, ATTN_SMEM_BYTES>>>(pQ, pcat);

  // 3. sa = cat @ Wo^T + bo
  gemm384_kernel<0><<<gemm_grid, 256>>>(pcat, Wo, bo, pt1);

  // 4. x1 = LN(x + sa)
  add_ln_kernel<<<MTOK, 128>>>(pt1, x, g1, be1, px1);

  // 5. h = relu(x1 @ W1^T + b1)
  gemm384_kernel<1><<<gemm_grid, 256>>>(px1, W1, b1, pt2);

  // 6. ff = h @ W2^T + b2
  gemm384_kernel<0><<<gemm_grid, 256>>>(pt2, W2, b2, pt1);

  // 7. out = LN(x1 + ff)
  add_ln_kernel<<<MTOK, 128>>>(pt1, px1, g2, be2, out);
}

// round 11
// speedup vs baseline: 1.7533x; 1.7533x over previous
#include <cuda_runtime.h>
#include <math.h>
#include <stdint.h>

#define EMBED 384
#define NHEADS 6
#define HS 64
#define BATCH 4
#define TT 2048
#define MTOK (BATCH * TT)   // 8192
#define ATTN_SCALE 0.125f   // 64^-0.5

// ---- scratch (no cudaMalloc allowed) ----
__device__ float g_Q[(size_t)BATCH * NHEADS * TT * HS];   // [B,H,T,64]
__device__ float g_cat[(size_t)MTOK * EMBED];
__device__ float g_t1[(size_t)MTOK * EMBED];
__device__ float g_x1[(size_t)MTOK * EMBED];
__device__ float g_t2[(size_t)MTOK * EMBED];

// ============================================================
// Tiled SGEMM: C[M,384] = A[M,384] @ W[384,384]^T (+bias)
// 128x64 CTA tile, 256 threads, 8x4 per-thread micro-tile.
// MODE 0: C = acc + bias
// MODE 1: C = relu(acc + bias)
// MODE 2: scatter acc into g_Q layout [B,H,T,64] (no bias)
// ============================================================
template <int MODE>
__global__ __launch_bounds__(256) void gemm384_kernel(
    const float* __restrict__ A, const float* __restrict__ W,
    const float* __restrict__ bias, float* __restrict__ C) {
  __shared__ float As[128][36];
  __shared__ float Bs[64][36];

  const int m0 = blockIdx.x * 128;
  const int n0 = blockIdx.y * 64;
  const int tid = threadIdx.x;
  const int tx = tid & 15;      // 16 -> N via tx + 16*j (j<4)
  const int ty = tid >> 4;      // 16 -> M via ty*8 + i (i<8)

  float acc[8][4];
#pragma unroll
  for (int i = 0; i < 8; i++)
#pragma unroll
    for (int j = 0; j < 4; j++) acc[i][j] = 0.0f;

  for (int k0 = 0; k0 < EMBED; k0 += 32) {
    // A tile: 128x32 = 1024 float4, 4/thread
#pragma unroll
    for (int q = 0; q < 4; q++) {
      int idx = tid + q * 256;
      int r = idx >> 3;                 // 0..127
      int c4 = (idx & 7) << 2;          // 0..28
      *(float4*)&As[r][c4] =
          *(const float4*)&A[(size_t)(m0 + r) * EMBED + k0 + c4];
    }
    // B tile: 64x32 = 512 float4, 2/thread
#pragma unroll
    for (int q = 0; q < 2; q++) {
      int idx = tid + q * 256;
      int r = idx >> 3;                 // 0..63
      int c4 = (idx & 7) << 2;
      *(float4*)&Bs[r][c4] =
          *(const float4*)&W[(size_t)(n0 + r) * EMBED + k0 + c4];
    }
    __syncthreads();

#pragma unroll
    for (int k4 = 0; k4 < 8; k4++) {
      float4 bv[4];
#pragma unroll
      for (int j = 0; j < 4; j++)
        bv[j] = *(float4*)&Bs[tx + 16 * j][k4 * 4];
#pragma unroll
      for (int i = 0; i < 8; i++) {
        float4 av = *(float4*)&As[ty * 8 + i][k4 * 4];
#pragma unroll
        for (int j = 0; j < 4; j++) {
          acc[i][j] += av.x * bv[j].x;
          acc[i][j] += av.y * bv[j].y;
          acc[i][j] += av.z * bv[j].z;
          acc[i][j] += av.w * bv[j].w;
        }
      }
    }
    __syncthreads();
  }

#pragma unroll
  for (int i = 0; i < 8; i++) {
    int m = m0 + ty * 8 + i;
#pragma unroll
    for (int j = 0; j < 4; j++) {
      int n = n0 + tx + 16 * j;
      float v = acc[i][j];
      if (MODE == 0) {
        C[(size_t)m * EMBED + n] = v + bias[n];
      } else if (MODE == 1) {
        C[(size_t)m * EMBED + n] = fmaxf(v + bias[n], 0.0f);
      } else {
        int b = m >> 11;            // /2048
        int t = m & 2047;
        int h = n >> 6;             // /64
        int d = n & 63;
        C[((size_t)(b * NHEADS + h) * TT + t) * HS + d] = v;
      }
    }
  }
}

// ============================================================
// Flash attention (fp32 SIMT), q = k = v (shared tensor).
// PROVEN R5 config: 64x64 tiles, 256 threads (16x16), 4x4 micro-tile.
// Added: reversed qi ordering (big causal blocks scheduled first).
// Masking matches reference exactly: s = dot*scale; upper-tri -> -inf;
// any remaining s == 0.0f -> -inf.
// ============================================================
#define ATTN_SMEM_FLOATS (64 * 64 + 64 * 68 + 64 * 64)
#define ATTN_SMEM_BYTES (ATTN_SMEM_FLOATS * 4)

__global__ __launch_bounds__(256) void attn_kernel(
    const float* __restrict__ Q, float* __restrict__ cat) {
  extern __shared__ float sm[];
  float* Qs = sm;                    // [64][64]
  float* Ks = sm + 64 * 64;          // [64][68] padded (strided reads)
  float* Ps = sm + 64 * 64 + 64 * 68;  // [64][64]

  const int bh = blockIdx.y;
  const int qi = gridDim.x - 1 - blockIdx.x;  // big blocks first
  const float* Qb = Q + (size_t)bh * TT * HS;

  const int tid = threadIdx.x;
  const int tx = tid & 15;
  const int ty = tid >> 4;

  // load Q tile (64x64 floats = 1024 float4)
#pragma unroll
  for (int q = 0; q < 4; q++) {
    int idx = tid + q * 256;
    int r = idx >> 4;
    int c4 = (idx & 15) << 2;
    *(float4*)&Qs[r * 64 + c4] =
        *(const float4*)&Qb[(size_t)(qi * 64 + r) * HS + c4];
  }

  float o[4][4];
  float mi[4], li[4];
#pragma unroll
  for (int i = 0; i < 4; i++) {
    mi[i] = -INFINITY;
    li[i] = 0.0f;
#pragma unroll
    for (int j = 0; j < 4; j++) o[i][j] = 0.0f;
  }

  for (int kt = 0; kt <= qi; kt++) {
    __syncthreads();  // protect Ks/Ps from previous iteration readers
#pragma unroll
    for (int q = 0; q < 4; q++) {
      int idx = tid + q * 256;
      int r = idx >> 4;
      int c4 = (idx & 15) << 2;
      *(float4*)&Ks[r * 68 + c4] =
          *(const float4*)&Qb[(size_t)(kt * 64 + r) * HS + c4];
    }
    __syncthreads();

    // ---- S = Q * K^T ----
    float s[4][4];
#pragma unroll
    for (int i = 0; i < 4; i++)
#pragma unroll
      for (int j = 0; j < 4; j++) s[i][j] = 0.0f;

#pragma unroll
    for (int d4 = 0; d4 < 16; d4++) {
      float4 av[4], bv[4];
#pragma unroll
      for (int i = 0; i < 4; i++)
        av[i] = *(float4*)&Qs[(ty * 4 + i) * 64 + d4 * 4];
#pragma unroll
      for (int j = 0; j < 4; j++)
        bv[j] = *(float4*)&Ks[(tx + 16 * j) * 68 + d4 * 4];
#pragma unroll
      for (int i = 0; i < 4; i++) {
#pragma unroll
        for (int j = 0; j < 4; j++) {
          s[i][j] += av[i].x * bv[j].x;
          s[i][j] += av[i].y * bv[j].y;
          s[i][j] += av[i].z * bv[j].z;
          s[i][j] += av[i].w * bv[j].w;
        }
      }
    }

    // ---- scale + mask (exact reference quirk) ----
#pragma unroll
    for (int i = 0; i < 4; i++) {
      int r = qi * 64 + ty * 4 + i;
#pragma unroll
      for (int j = 0; j < 4; j++) {
        int c = kt * 64 + tx + 16 * j;
        float v = s[i][j] * ATTN_SCALE;
        if (c > r || v == 0.0f) v = -INFINITY;
        s[i][j] = v;
      }
    }

    // ---- online softmax update ----
#pragma unroll
    for (int i = 0; i < 4; i++) {
      float rm = fmaxf(fmaxf(s[i][0], s[i][1]), fmaxf(s[i][2], s[i][3]));
#pragma unroll
      for (int off = 8; off > 0; off >>= 1)
        rm = fmaxf(rm, __shfl_xor_sync(0xffffffffu, rm, off));
      float nm = fmaxf(mi[i], rm);
      float alpha = (mi[i] == -INFINITY) ? 0.0f : __expf(mi[i] - nm);
      float psum = 0.0f;
#pragma unroll
      for (int j = 0; j < 4; j++) {
        float p = __expf(s[i][j] - nm);
        s[i][j] = p;
        psum += p;
      }
#pragma unroll
      for (int off = 8; off > 0; off >>= 1)
        psum += __shfl_xor_sync(0xffffffffu, psum, off);
      li[i] = li[i] * alpha + psum;
      mi[i] = nm;
#pragma unroll
      for (int j = 0; j < 4; j++) o[i][j] *= alpha;
    }

    // ---- stage P, then O += P * V (V == K tile) ----
#pragma unroll
    for (int i = 0; i < 4; i++)
#pragma unroll
      for (int j = 0; j < 4; j++)
        Ps[(ty * 4 + i) * 64 + tx + 16 * j] = s[i][j];
    __syncthreads();

#pragma unroll
    for (int k4 = 0; k4 < 16; k4++) {
      float4 p4[4];
#pragma unroll
      for (int i = 0; i < 4; i++)
        p4[i] = *(float4*)&Ps[(ty * 4 + i) * 64 + k4 * 4];
#pragma unroll
      for (int kk = 0; kk < 4; kk++) {
        int k = k4 * 4 + kk;
        float v0 = Ks[k * 68 + tx];
        float v1 = Ks[k * 68 + tx + 16];
        float v2 = Ks[k * 68 + tx + 32];
        float v3 = Ks[k * 68 + tx + 48];
#pragma unroll
        for (int i = 0; i < 4; i++) {
          float pv = ((const float*)&p4[i])[kk];
          o[i][0] += pv * v0;
          o[i][1] += pv * v1;
          o[i][2] += pv * v2;
          o[i][3] += pv * v3;
        }
      }
    }
  }

  // ---- epilogue: normalize and write into concat layout [B,T,384] ----
  const int b = bh / NHEADS;
  const int h = bh % NHEADS;
#pragma unroll
  for (int i = 0; i < 4; i++) {
    float inv = 1.0f / li[i];
    int t = qi * 64 + ty * 4 + i;
    size_t base = ((size_t)(b * TT + t)) * EMBED + h * HS;
#pragma unroll
    for (int j = 0; j < 4; j++)
      cat[base + tx + 16 * j] = o[i][j] * inv;
  }
}

// ============================================================
// out = LayerNorm(a + res) * g + be   (one block per token row)
// ============================================================
__global__ __launch_bounds__(128) void add_ln_kernel(
    const float* __restrict__ a, const float* __restrict__ res,
    const float* __restrict__ g, const float* __restrict__ be,
    float* __restrict__ out) {
  __shared__ float red[8];
  const int row = blockIdx.x;
  const int tid = threadIdx.x;
  const size_t base = (size_t)row * EMBED;

  float v[3];
#pragma unroll
  for (int q = 0; q < 3; q++) {
    int c = tid + q * 128;
    v[q] = a[base + c] + res[base + c];
  }

  float s = v[0] + v[1] + v[2];
#pragma unroll
  for (int off = 16; off > 0; off >>= 1)
    s += __shfl_xor_sync(0xffffffffu, s, off);
  if ((tid & 31) == 0) red[tid >> 5] = s;
  __syncthreads();
  float mu = (red[0] + red[1] + red[2] + red[3]) * (1.0f / EMBED);

  float d0 = v[0] - mu, d1 = v[1] - mu, d2 = v[2] - mu;
  float sq = d0 * d0 + d1 * d1 + d2 * d2;
#pragma unroll
  for (int off = 16; off > 0; off >>= 1)
    sq += __shfl_xor_sync(0xffffffffu, sq, off);
  if ((tid & 31) == 0) red[4 + (tid >> 5)] = sq;
  __syncthreads();
  float var = (red[4] + red[5] + red[6] + red[7]) * (1.0f / EMBED);
  float inv = rsqrtf(var + 1e-5f);

  out[base + tid]       = d0 * inv * g[tid]       + be[tid];
  out[base + tid + 128] = d1 * inv * g[tid + 128] + be[tid + 128];
  out[base + tid + 256] = d2 * inv * g[tid + 256] + be[tid + 256];
}

// ============================================================
// launch
// ============================================================
extern "C" void kernel_launch(void* const* d_in, const int* in_sizes, int n_in,
                              void* d_out, int out_size) {
  const float* x   = (const float*)d_in[0];
  const float* Wq  = (const float*)d_in[1];
  const float* Wo  = (const float*)d_in[2];
  const float* bo  = (const float*)d_in[3];
  const float* W1  = (const float*)d_in[4];
  const float* b1  = (const float*)d_in[5];
  const float* W2  = (const float*)d_in[6];
  const float* b2  = (const float*)d_in[7];
  const float* g1  = (const float*)d_in[8];
  const float* be1 = (const float*)d_in[9];
  const float* g2  = (const float*)d_in[10];
  const float* be2 = (const float*)d_in[11];
  float* out = (float*)d_out;

  float *pQ, *pcat, *pt1, *px1, *pt2;
  cudaGetSymbolAddress((void**)&pQ, g_Q);
  cudaGetSymbolAddress((void**)&pcat, g_cat);
  cudaGetSymbolAddress((void**)&pt1, g_t1);
  cudaGetSymbolAddress((void**)&px1, g_x1);
  cudaGetSymbolAddress((void**)&pt2, g_t2);

  cudaFuncSetAttribute(attn_kernel,
                       cudaFuncAttributeMaxDynamicSharedMemorySize,
                       ATTN_SMEM_BYTES);

  dim3 gemm_grid(MTOK / 128, EMBED / 64);

  // 1. q = x @ Wq^T, scattered to [B,H,T,64]
  gemm384_kernel<2><<<gemm_grid, 256>>>(x, Wq, nullptr, pQ);

  // 2. causal self-attention (q=k=v), output in concat layout
  attn_kernel<<<dim3(TT / 64, BATCH * NHEADS), 256, ATTN_SMEM_BYTES>>>(pQ, pcat);

  // 3. sa = cat @ Wo^T + bo
  gemm384_kernel<0><<<gemm_grid, 256>>>(pcat, Wo, bo, pt1);

  // 4. x1 = LN(x + sa)
  add_ln_kernel<<<MTOK, 128>>>(pt1, x, g1, be1, px1);

  // 5. h = relu(x1 @ W1^T + b1)
  gemm384_kernel<1><<<gemm_grid, 256>>>(px1, W1, b1, pt2);

  // 6. ff = h @ W2^T + b2
  gemm384_kernel<0><<<gemm_grid, 256>>>(pt2, W2, b2, pt1);

  // 7. out = LN(x1 + ff)
  add_ln_kernel<<<MTOK, 128>>>(pt1, px1, g2, be2, out);
}

// round 13
// speedup vs baseline: 1.8326x; 1.0452x over previous
#include <cuda_runtime.h>
#include <math.h>
#include <stdint.h>

#define EMBED 384
#define NHEADS 6
#define HS 64
#define BATCH 4
#define TT 2048
#define MTOK (BATCH * TT)   // 8192
#define ATTN_SCALE 0.125f   // 64^-0.5

// ---- scratch (no cudaMalloc allowed) ----
__device__ float g_Q[(size_t)BATCH * NHEADS * TT * HS];   // [B,H,T,64]
__device__ float g_cat[(size_t)MTOK * EMBED];
__device__ float g_t1[(size_t)MTOK * EMBED];
__device__ float g_x1[(size_t)MTOK * EMBED];
__device__ float g_t2[(size_t)MTOK * EMBED];

// ============================================================
// Tiled SGEMM: C[M,384] = A[M,384] @ W[384,384]^T (+bias)
// 128x64 CTA tile, 256 threads, 8x4 per-thread micro-tile.
// MODE 0: C = acc + bias
// MODE 1: C = relu(acc + bias)
// MODE 2: scatter acc into g_Q layout [B,H,T,64] (no bias)
// ============================================================
template <int MODE>
__global__ __launch_bounds__(256) void gemm384_kernel(
    const float* __restrict__ A, const float* __restrict__ W,
    const float* __restrict__ bias, float* __restrict__ C) {
  __shared__ float As[128][36];
  __shared__ float Bs[64][36];

  const int m0 = blockIdx.x * 128;
  const int n0 = blockIdx.y * 64;
  const int tid = threadIdx.x;
  const int tx = tid & 15;      // 16 -> N via tx + 16*j (j<4)
  const int ty = tid >> 4;      // 16 -> M via ty*8 + i (i<8)

  float acc[8][4];
#pragma unroll
  for (int i = 0; i < 8; i++)
#pragma unroll
    for (int j = 0; j < 4; j++) acc[i][j] = 0.0f;

  for (int k0 = 0; k0 < EMBED; k0 += 32) {
    // A tile: 128x32 = 1024 float4, 4/thread
#pragma unroll
    for (int q = 0; q < 4; q++) {
      int idx = tid + q * 256;
      int r = idx >> 3;                 // 0..127
      int c4 = (idx & 7) << 2;          // 0..28
      *(float4*)&As[r][c4] =
          *(const float4*)&A[(size_t)(m0 + r) * EMBED + k0 + c4];
    }
    // B tile: 64x32 = 512 float4, 2/thread
#pragma unroll
    for (int q = 0; q < 2; q++) {
      int idx = tid + q * 256;
      int r = idx >> 3;                 // 0..63
      int c4 = (idx & 7) << 2;
      *(float4*)&Bs[r][c4] =
          *(const float4*)&W[(size_t)(n0 + r) * EMBED + k0 + c4];
    }
    __syncthreads();

#pragma unroll
    for (int k4 = 0; k4 < 8; k4++) {
      float4 bv[4];
#pragma unroll
      for (int j = 0; j < 4; j++)
        bv[j] = *(float4*)&Bs[tx + 16 * j][k4 * 4];
#pragma unroll
      for (int i = 0; i < 8; i++) {
        float4 av = *(float4*)&As[ty * 8 + i][k4 * 4];
#pragma unroll
        for (int j = 0; j < 4; j++) {
          acc[i][j] += av.x * bv[j].x;
          acc[i][j] += av.y * bv[j].y;
          acc[i][j] += av.z * bv[j].z;
          acc[i][j] += av.w * bv[j].w;
        }
      }
    }
    __syncthreads();
  }

#pragma unroll
  for (int i = 0; i < 8; i++) {
    int m = m0 + ty * 8 + i;
#pragma unroll
    for (int j = 0; j < 4; j++) {
      int n = n0 + tx + 16 * j;
      float v = acc[i][j];
      if (MODE == 0) {
        C[(size_t)m * EMBED + n] = v + bias[n];
      } else if (MODE == 1) {
        C[(size_t)m * EMBED + n] = fmaxf(v + bias[n], 0.0f);
      } else {
        int b = m >> 11;            // /2048
        int t = m & 2047;
        int h = n >> 6;             // /64
        int d = n & 63;
        C[((size_t)(b * NHEADS + h) * TT + t) * HS + d] = v;
      }
    }
  }
}

// ============================================================
// Flash attention (fp32 SIMT), q = k = v (shared tensor).
// 64 query rows x 128 keys per chunk. 256 threads (16x16).
// S phase: 4x8 micro-tile (cols = tx + 16*j, j<8).
// PV phase: 4x4 micro-tile (o cols = tx*4..tx*4+3, vector v loads).
// Masking matches reference exactly: s = dot*scale; upper-tri -> -inf;
// any remaining s == 0.0f -> -inf.
// ============================================================
#define KC 128
#define ATTN_SMEM_FLOATS (64 * 64 + KC * 68 + 64 * KC)
#define ATTN_SMEM_BYTES (ATTN_SMEM_FLOATS * 4)

__global__ __launch_bounds__(256) void attn_kernel(
    const float* __restrict__ Q, float* __restrict__ cat) {
  extern __shared__ float sm[];
  float* Qs = sm;                          // [64][64]
  float* Ks = sm + 64 * 64;                // [128][68] padded
  float* Ps = sm + 64 * 64 + KC * 68;      // [64][128]

  const int bh = blockIdx.y;
  const int qi = gridDim.x - 1 - blockIdx.x;  // big blocks first
  const float* Qb = Q + (size_t)bh * TT * HS;

  const int tid = threadIdx.x;
  const int tx = tid & 15;
  const int ty = tid >> 4;

  // load Q tile (64x64 floats = 1024 float4)
#pragma unroll
  for (int q = 0; q < 4; q++) {
    int idx = tid + q * 256;
    int r = idx >> 4;
    int c4 = (idx & 15) << 2;
    *(float4*)&Qs[r * 64 + c4] =
        *(const float4*)&Qb[(size_t)(qi * 64 + r) * HS + c4];
  }

  float o[4][4];
  float mi[4], li[4];
#pragma unroll
  for (int i = 0; i < 4; i++) {
    mi[i] = -INFINITY;
    li[i] = 0.0f;
#pragma unroll
    for (int j = 0; j < 4; j++) o[i][j] = 0.0f;
  }

  const int nc = (qi >> 1) + 1;   // 128-key chunks covering keys <= qi*64+63

  for (int kt = 0; kt < nc; kt++) {
    __syncthreads();  // protect Ks/Ps from previous iteration readers
    // load K chunk: 128 rows x 64 = 2048 float4, 8/thread
#pragma unroll
    for (int q = 0; q < 8; q++) {
      int idx = tid + q * 256;
      int r = idx >> 4;                 // 0..127
      int c4 = (idx & 15) << 2;
      *(float4*)&Ks[r * 68 + c4] =
          *(const float4*)&Qb[(size_t)(kt * KC + r) * HS + c4];
    }
    __syncthreads();

    // ---- S = Q * K^T  (64 rows x 128 keys, 4x8 per thread) ----
    float s[4][8];
#pragma unroll
    for (int i = 0; i < 4; i++)
#pragma unroll
      for (int j = 0; j < 8; j++) s[i][j] = 0.0f;

#pragma unroll
    for (int d4 = 0; d4 < 16; d4++) {
      float4 av[4], bv[8];
#pragma unroll
      for (int i = 0; i < 4; i++)
        av[i] = *(float4*)&Qs[(ty * 4 + i) * 64 + d4 * 4];
#pragma unroll
      for (int j = 0; j < 8; j++)
        bv[j] = *(float4*)&Ks[(tx + 16 * j) * 68 + d4 * 4];
#pragma unroll
      for (int i = 0; i < 4; i++) {
#pragma unroll
        for (int j = 0; j < 8; j++) {
          s[i][j] += av[i].x * bv[j].x;
          s[i][j] += av[i].y * bv[j].y;
          s[i][j] += av[i].z * bv[j].z;
          s[i][j] += av[i].w * bv[j].w;
        }
      }
    }

    // ---- scale + mask (exact reference quirk) ----
#pragma unroll
    for (int i = 0; i < 4; i++) {
      int r = qi * 64 + ty * 4 + i;
#pragma unroll
      for (int j = 0; j < 8; j++) {
        int c = kt * KC + tx + 16 * j;
        float v = s[i][j] * ATTN_SCALE;
        if (c > r || v == 0.0f) v = -INFINITY;
        s[i][j] = v;
      }
    }

    // ---- online softmax update (16-lane reductions over tx) ----
#pragma unroll
    for (int i = 0; i < 4; i++) {
      float rm = s[i][0];
#pragma unroll
      for (int j = 1; j < 8; j++) rm = fmaxf(rm, s[i][j]);
#pragma unroll
      for (int off = 8; off > 0; off >>= 1)
        rm = fmaxf(rm, __shfl_xor_sync(0xffffffffu, rm, off));
      float nm = fmaxf(mi[i], rm);
      float alpha = (mi[i] == -INFINITY) ? 0.0f : __expf(mi[i] - nm);
      float psum = 0.0f;
#pragma unroll
      for (int j = 0; j < 8; j++) {
        float p = __expf(s[i][j] - nm);
        s[i][j] = p;
        psum += p;
      }
#pragma unroll
      for (int off = 8; off > 0; off >>= 1)
        psum += __shfl_xor_sync(0xffffffffu, psum, off);
      li[i] = li[i] * alpha + psum;
      mi[i] = nm;
#pragma unroll
      for (int j = 0; j < 4; j++) o[i][j] *= alpha;
    }

    // ---- stage P, then O += P * V (V == K chunk) ----
#pragma unroll
    for (int i = 0; i < 4; i++)
#pragma unroll
      for (int j = 0; j < 8; j++)
        Ps[(ty * 4 + i) * KC + tx + 16 * j] = s[i][j];
    __syncthreads();

#pragma unroll
    for (int k4 = 0; k4 < KC / 4; k4++) {
      float4 p4[4];
#pragma unroll
      for (int i = 0; i < 4; i++)
        p4[i] = *(float4*)&Ps[(ty * 4 + i) * KC + k4 * 4];
#pragma unroll
      for (int kk = 0; kk < 4; kk++) {
        int k = k4 * 4 + kk;
        float4 v = *(float4*)&Ks[k * 68 + tx * 4];
#pragma unroll
        for (int i = 0; i < 4; i++) {
          float pv = ((const float*)&p4[i])[kk];
          o[i][0] += pv * v.x;
          o[i][1] += pv * v.y;
          o[i][2] += pv * v.z;
          o[i][3] += pv * v.w;
        }
      }
    }
  }

  // ---- epilogue: normalize and write into concat layout [B,T,384] ----
  const int b = bh / NHEADS;
  const int h = bh % NHEADS;
#pragma unroll
  for (int i = 0; i < 4; i++) {
    float inv = 1.0f / li[i];
    int t = qi * 64 + ty * 4 + i;
    size_t base = ((size_t)(b * TT + t)) * EMBED + h * HS;
    float4 ov;
    ov.x = o[i][0] * inv;
    ov.y = o[i][1] * inv;
    ov.z = o[i][2] * inv;
    ov.w = o[i][3] * inv;
    *(float4*)&cat[base + tx * 4] = ov;
  }
}

// ============================================================
// out = LayerNorm(a + res) * g + be   (one block per token row)
// ============================================================
__global__ __launch_bounds__(128) void add_ln_kernel(
    const float* __restrict__ a, const float* __restrict__ res,
    const float* __restrict__ g, const float* __restrict__ be,
    float* __restrict__ out) {
  __shared__ float red[8];
  const int row = blockIdx.x;
  const int tid = threadIdx.x;
  const size_t base = (size_t)row * EMBED;

  float v[3];
#pragma unroll
  for (int q = 0; q < 3; q++) {
    int c = tid + q * 128;
    v[q] = a[base + c] + res[base + c];
  }

  float s = v[0] + v[1] + v[2];
#pragma unroll
  for (int off = 16; off > 0; off >>= 1)
    s += __shfl_xor_sync(0xffffffffu, s, off);
  if ((tid & 31) == 0) red[tid >> 5] = s;
  __syncthreads();
  float mu = (red[0] + red[1] + red[2] + red[3]) * (1.0f / EMBED);

  float d0 = v[0] - mu, d1 = v[1] - mu, d2 = v[2] - mu;
  float sq = d0 * d0 + d1 * d1 + d2 * d2;
#pragma unroll
  for (int off = 16; off > 0; off >>= 1)
    sq += __shfl_xor_sync(0xffffffffu, sq, off);
  if ((tid & 31) == 0) red[4 + (tid >> 5)] = sq;
  __syncthreads();
  float var = (red[4] + red[5] + red[6] + red[7]) * (1.0f / EMBED);
  float inv = rsqrtf(var + 1e-5f);

  out[base + tid]       = d0 * inv * g[tid]       + be[tid];
  out[base + tid + 128] = d1 * inv * g[tid + 128] + be[tid + 128];
  out[base + tid + 256] = d2 * inv * g[tid + 256] + be[tid + 256];
}

// ============================================================
// launch
// ============================================================
extern "C" void kernel_launch(void* const* d_in, const int* in_sizes, int n_in,
                              void* d_out, int out_size) {
  const float* x   = (const float*)d_in[0];
  const float* Wq  = (const float*)d_in[1];
  const float* Wo  = (const float*)d_in[2];
  const float* bo  = (const float*)d_in[3];
  const float* W1  = (const float*)d_in[4];
  const float* b1  = (const float*)d_in[5];
  const float* W2  = (const float*)d_in[6];
  const float* b2  = (const float*)d_in[7];
  const float* g1  = (const float*)d_in[8];
  const float* be1 = (const float*)d_in[9];
  const float* g2  = (const float*)d_in[10];
  const float* be2 = (const float*)d_in[11];
  float* out = (float*)d_out;

  float *pQ, *pcat, *pt1, *px1, *pt2;
  cudaGetSymbolAddress((void**)&pQ, g_Q);
  cudaGetSymbolAddress((void**)&pcat, g_cat);
  cudaGetSymbolAddress((void**)&pt1, g_t1);
  cudaGetSymbolAddress((void**)&px1, g_x1);
  cudaGetSymbolAddress((void**)&pt2, g_t2);

  cudaFuncSetAttribute(attn_kernel,
                       cudaFuncAttributeMaxDynamicSharedMemorySize,
                       ATTN_SMEM_BYTES);

  dim3 gemm_grid(MTOK / 128, EMBED / 64);

  // 1. q = x @ Wq^T, scattered to [B,H,T,64]
  gemm384_kernel<2><<<gemm_grid, 256>>>(x, Wq, nullptr, pQ);

  // 2. causal self-attention (q=k=v), output in concat layout
  attn_kernel<<<dim3(TT / 64, BATCH * NHEADS), 256, ATTN_SMEM_BYTES>>>(pQ, pcat);

  // 3. sa = cat @ Wo^T + bo
  gemm384_kernel<0><<<gemm_grid, 256>>>(pcat, Wo, bo, pt1);

  // 4. x1 = LN(x + sa)
  add_ln_kernel<<<MTOK, 128>>>(pt1, x, g1, be1, px1);

  // 5. h = relu(x1 @ W1^T + b1)
  gemm384_kernel<1><<<gemm_grid, 256>>>(px1, W1, b1, pt2);

  // 6. ff = h @ W2^T + b2
  gemm384_kernel<0><<<gemm_grid, 256>>>(pt2, W2, b2, pt1);

  // 7. out = LN(x1 + ff)
  add_ln_kernel<<<MTOK, 128>>>(pt1, px1, g2, be2, out);
}